// round 12
// baseline (speedup 1.0000x reference)
#include <cuda_runtime.h>
#include <cuda_bf16.h>
#include <stdint.h>

// Shapes (fixed by the problem)
#define N_SEQ 256      // batch
#define NC    3        // coord channels
#define NT    256      // time
#define NV    25       // joints
#define NK    64       // structure elements
#define INFK  0xFFFFFFFFu

// MST smem layout: R rows of the key matrix at stride 257 words, plus a
// pre-packed (TAIL x 43) tail-tail block. Everything else via symmetry.
#define RZ    214              // rows resident (stride 257)
#define TAIL  (N_SEQ - RZ)     // 42
#define SROW  257              // word stride (== 1 mod 32 -> conflict-free transpose)
#define TBASE (RZ * SROW)      // word offset of tail-tail block
#define TROW  43               // tail block word stride
#define MST_SMEM_WORDS (TBASE + TAIL * TROW)

// Scratch (device globals — no allocation allowed)
__device__ __align__(16) float    g_feat[N_SEQ * NV];
__device__ __align__(16) unsigned g_Dk[N_SEQ * N_SEQ];   // packed (dist24|idx8) keys

// ---------------------------------------------------------------------------
// K1: per-sequence mean over (c,t), then feat[n,j] = || m[n,:] - m[n,j] ||
// block = 400 threads: element t+400k has joint (t+400k)%25 == t%25 (400%25==0)
// -> every thread accumulates ONE joint, loads fully coalesced, all lanes busy.
// ---------------------------------------------------------------------------
__global__ __launch_bounds__(400) void k_meanfeat(const float* __restrict__ x) {
    __shared__ float s_part[16][NV];
    __shared__ float s_m[NV];

    const int n   = blockIdx.x;
    const int tid = threadIdx.x;            // 0..399
    const float* p = x + (size_t)n * (NC * NT * NV) + tid;

    float a0 = 0.f, a1 = 0.f, a2 = 0.f, a3 = 0.f;
    float a4 = 0.f, a5 = 0.f, a6 = 0.f, a7 = 0.f;
    #pragma unroll
    for (int i = 0; i < 6; i++) {           // 48 = 19200/400 elements/thread
        const float* q = p + i * 8 * 400;
        a0 += q[0 * 400]; a1 += q[1 * 400]; a2 += q[2 * 400]; a3 += q[3 * 400];
        a4 += q[4 * 400]; a5 += q[5 * 400]; a6 += q[6 * 400]; a7 += q[7 * 400];
    }
    s_part[tid / 25][tid % 25] = ((a0 + a1) + (a2 + a3)) + ((a4 + a5) + (a6 + a7));
    __syncthreads();

    if (tid < NV) {
        float s = 0.f;
        #pragma unroll
        for (int g = 0; g < 16; g++) s += s_part[g][tid];
        s_m[tid] = s * (1.0f / (NC * NT));
    }
    __syncthreads();

    if (tid < NV) {
        const float mj = s_m[tid];
        float ss = 0.f;
        #pragma unroll
        for (int i = 0; i < NV; i++) {
            float d = s_m[i] - mj;
            ss += d * d;
        }
        g_feat[n * NV + tid] = sqrtf(ss);
    }
}

// ---------------------------------------------------------------------------
// K2: global min/max normalization + PACKED distance-key matrix row i
// key[i][j] = (float_bits(D[i][j]) & 0xFFFFFF00) | j
// ---------------------------------------------------------------------------
__global__ __launch_bounds__(256) void k_dist() {
    const int i   = blockIdx.x;
    const int tid = threadIdx.x;

    __shared__ float sf[N_SEQ * NV];
    __shared__ unsigned smin[8], smax[8];

    for (int idx = tid; idx < N_SEQ * NV; idx += 256)
        sf[idx] = g_feat[idx];
    __syncthreads();

    unsigned lmin = INFK, lmax = 0u;
    for (int idx = tid; idx < N_SEQ * NV; idx += 256) {
        unsigned b = __float_as_uint(sf[idx]);
        lmin = min(lmin, b);
        lmax = max(lmax, b);
    }
    lmin = __reduce_min_sync(0xFFFFFFFFu, lmin);
    lmax = __reduce_max_sync(0xFFFFFFFFu, lmax);
    if ((tid & 31) == 0) { smin[tid >> 5] = lmin; smax[tid >> 5] = lmax; }
    __syncthreads();
    unsigned gmn = smin[0], gmx = smax[0];
    #pragma unroll
    for (int w = 1; w < 8; w++) { gmn = min(gmn, smin[w]); gmx = max(gmx, smax[w]); }
    const float inv = 1.0f / (__uint_as_float(gmx) - __uint_as_float(gmn));

    float fi[NV];
    #pragma unroll
    for (int d = 0; d < NV; d++) fi[d] = sf[i * NV + d];

    float ss = 0.f;
    #pragma unroll
    for (int d = 0; d < NV; d++) {
        float df = (fi[d] - sf[tid * NV + d]) * inv;
        ss += df * df;
    }
    g_Dk[i * N_SEQ + tid] = (__float_as_uint(sqrtf(ss)) & 0xFFFFFF00u) | (unsigned)tid;
}

// ---------------------------------------------------------------------------
// K3: single-warp Prim MST, 100% SMEM row fetches via symmetry:
//   node k -> lane (k&31), slot (k>>5)   [interleaved ownership]
//   j <  RZ : direct   sBuf[j*257 + k]                (banks j+l: conflict-free)
//   j >= RZ : k <  RZ : sBuf[k*257 + j]  + repack idx (banks l+j: conflict-free)
//             k >= RZ : sBuf[TBASE + (j-RZ)*43 + (k-RZ)]  (pre-packed)
// Branchless index SELs; no generic/global loads; no L2 on the chain.
// ---------------------------------------------------------------------------
__global__ __launch_bounds__(512) void k_mst(const float* __restrict__ centres,
                                             const float* __restrict__ sharp,
                                             float* __restrict__ out) {
    extern __shared__ __align__(16) unsigned sBuf[];
    __shared__ float deaths[N_SEQ - 1];
    __shared__ float s_part2[8][NK];

    const int tid = threadIdx.x;

    // Fill main rows (coalesced LDG.32, near-conflict-free STS.32)
    #pragma unroll 4
    for (int idx = tid; idx < RZ * N_SEQ; idx += 512)
        sBuf[(idx >> 8) * SROW + (idx & 255)] = g_Dk[idx];
    // Fill tail-tail block (already packed with col idx)
    for (int idx = tid; idx < TAIL * TAIL; idx += 512) {
        const int a = idx / TAIL, b = idx - a * TAIL;
        sBuf[TBASE + a * TROW + b] = g_Dk[(RZ + a) * N_SEQ + (RZ + b)];
    }
    __syncthreads();

    if (tid < 32) {
        const int lane = tid;

        // per-slot node constants
        #define NODE(T) (lane + 32 * (T))
        // init keys from row 0 of the matrix
        #define KINIT(T) unsigned k##T = sBuf[NODE(T)];
        KINIT(0) KINIT(1) KINIT(2) KINIT(3) KINIT(4) KINIT(5) KINIT(6) KINIT(7)
        #undef KINIT
        if (lane == 0) k0 = INFK;                 // node 0 starts in the tree

        unsigned m = min(min(min(k0, k1), min(k2, k3)),
                         min(min(k4, k5), min(k6, k7)));

        for (int it = 0; it < N_SEQ - 1; ++it) {
            unsigned g;
            asm volatile("redux.sync.min.u32 %0, %1, 0xffffffff;"
                         : "=r"(g) : "r"(m));
            const int j = (int)(g & 0xFFu);
            if (lane == 0) deaths[it] = __uint_as_float(g & 0xFFFFFF00u);

            const bool jin       = (j < RZ);
            const unsigned rowB  = (unsigned)j * SROW;           // direct row base
            const unsigned tailB = TBASE + (unsigned)(j - RZ) * TROW; // tail row base

            // per-slot candidate fetch (all LDS.32, conflict-free)
            #define FETCH(T, TAILPRED)                                          \
                unsigned v##T;                                                   \
                {                                                                \
                    const unsigned idxA = rowB + (unsigned)NODE(T);              \
                    const unsigned idxB = (TAILPRED)                             \
                        ? (tailB + (unsigned)(NODE(T) - RZ))                     \
                        : ((unsigned)NODE(T) * SROW + (unsigned)j);              \
                    const unsigned raw  = sBuf[jin ? idxA : idxB];               \
                    v##T = (jin || (TAILPRED))                                   \
                        ? raw                                                    \
                        : ((raw & 0xFFFFFF00u) | (unsigned)NODE(T));             \
                }
            FETCH(0, false) FETCH(1, false) FETCH(2, false)
            FETCH(3, false) FETCH(4, false) FETCH(5, false)
            FETCH(6, (NODE(6) >= RZ))   // slot 6 straddles RZ=214 (lane>=22)
            FETCH(7, true)              // nodes 224..255 always tail
            #undef FETCH

            // off-chain-ish: remove extracted node j, recompute fixed min
            const bool own = ((j & 31) == lane);
            const int  tj  = j >> 5;
            #define RM(T) k##T = (own && (tj == (T))) ? INFK : k##T;
            RM(0) RM(1) RM(2) RM(3) RM(4) RM(5) RM(6) RM(7)
            #undef RM
            const unsigned mfix = min(min(min(k0, k1), min(k2, k3)),
                                      min(min(k4, k5), min(k6, k7)));

            // mask in-tree nodes, merge candidates
            #define CM(T)                                                \
                const unsigned c##T = (k##T == INFK) ? INFK : v##T;      \
                k##T = min(k##T, c##T);
            CM(0) CM(1) CM(2) CM(3) CM(4) CM(5) CM(6) CM(7)
            #undef CM
            const unsigned mc = min(min(min(c0, c1), min(c2, c3)),
                                    min(min(c4, c5), min(c6, c7)));
            m = min(mfix, mc);
        }
        #undef NODE
    }
    __syncthreads();

    // ---- Structure element layer ----
    {
        const int k    = tid & (NK - 1);
        const int part = tid >> 6;            // 0..7
        const float c0 = centres[2 * k];
        const float c1 = centres[2 * k + 1];
        const float s0 = sharp[2 * k];
        const float s1 = sharp[2 * k + 1];
        const float a  = c0 * c0 * s0 * s0;
        const float b  = s1 * s1;

        float acc = 0.f;
        const int e0 = part * 32;
        const int e1 = min(N_SEQ - 1, e0 + 32);
        for (int e = e0; e < e1; e++) {
            float d = deaths[e] - c1;
            acc += __expf(-(a + d * d * b));
        }
        s_part2[part][k] = acc;
    }
    __syncthreads();
    if (tid < NK) {
        float s = 0.f;
        #pragma unroll
        for (int p = 0; p < 8; p++) s += s_part2[p][tid];
        out[tid] = s;
    }
}

// ---------------------------------------------------------------------------
extern "C" void kernel_launch(void* const* d_in, const int* in_sizes, int n_in,
                              void* d_out, int out_size) {
    const float* x       = (const float*)d_in[0];
    const float* centres = (const float*)d_in[1];
    const float* sharp   = (const float*)d_in[2];
    float*       out     = (float*)d_out;

    const size_t mst_smem = (size_t)MST_SMEM_WORDS * sizeof(unsigned);  // ~227.2 KB
    cudaFuncSetAttribute(k_mst, cudaFuncAttributeMaxDynamicSharedMemorySize, (int)mst_smem);

    k_meanfeat<<<N_SEQ, 400>>>(x);
    k_dist<<<N_SEQ, 256>>>();
    k_mst<<<1, 512, mst_smem>>>(centres, sharp, out);
}

// round 13
// speedup vs baseline: 1.0050x; 1.0050x over previous
#include <cuda_runtime.h>
#include <cuda_bf16.h>
#include <stdint.h>

// Shapes (fixed by the problem)
#define N_SEQ 256      // batch
#define NC    3        // coord channels
#define NT    256      // time
#define NV    25       // joints
#define NK    64       // structure elements
#define INFK  0xFFFFFFFFu

// MST smem layout: R rows of the key matrix at stride 257 words, plus a
// pre-packed (TAIL x 43) tail-tail block. Everything else via symmetry.
#define RZ    214              // rows resident (stride 257)
#define TAIL  (N_SEQ - RZ)     // 42
#define SROW  257              // word stride (== 1 mod 32 -> conflict-free transpose)
#define TBASE (RZ * SROW)      // word offset of tail-tail block
#define TROW  43               // tail block word stride
#define MST_SMEM_WORDS (TBASE + TAIL * TROW)

// Scratch (device globals — no allocation allowed)
__device__ __align__(16) float    g_feat[N_SEQ * NV];
__device__ __align__(16) unsigned g_Dk[N_SEQ * N_SEQ];   // packed (dist24|idx8) keys

// ---------------------------------------------------------------------------
// K1: per-sequence mean over (c,t), then feat[n,j] = || m[n,:] - m[n,j] ||
// block = 400 threads: element t+400k has joint (t+400k)%25 == t%25 (400%25==0)
// -> every thread accumulates ONE joint, loads fully coalesced, all lanes busy.
// ---------------------------------------------------------------------------
__global__ __launch_bounds__(400) void k_meanfeat(const float* __restrict__ x) {
    __shared__ float s_part[16][NV];
    __shared__ float s_m[NV];

    const int n   = blockIdx.x;
    const int tid = threadIdx.x;            // 0..399
    const float* p = x + (size_t)n * (NC * NT * NV) + tid;

    float a0 = 0.f, a1 = 0.f, a2 = 0.f, a3 = 0.f;
    float a4 = 0.f, a5 = 0.f, a6 = 0.f, a7 = 0.f;
    #pragma unroll
    for (int i = 0; i < 6; i++) {           // 48 = 19200/400 elements/thread
        const float* q = p + i * 8 * 400;
        a0 += q[0 * 400]; a1 += q[1 * 400]; a2 += q[2 * 400]; a3 += q[3 * 400];
        a4 += q[4 * 400]; a5 += q[5 * 400]; a6 += q[6 * 400]; a7 += q[7 * 400];
    }
    s_part[tid / 25][tid % 25] = ((a0 + a1) + (a2 + a3)) + ((a4 + a5) + (a6 + a7));
    __syncthreads();

    if (tid < NV) {
        float s = 0.f;
        #pragma unroll
        for (int g = 0; g < 16; g++) s += s_part[g][tid];
        s_m[tid] = s * (1.0f / (NC * NT));
    }
    __syncthreads();

    if (tid < NV) {
        const float mj = s_m[tid];
        float ss = 0.f;
        #pragma unroll
        for (int i = 0; i < NV; i++) {
            float d = s_m[i] - mj;
            ss += d * d;
        }
        g_feat[n * NV + tid] = sqrtf(ss);
    }
}

// ---------------------------------------------------------------------------
// K2: global min/max normalization + PACKED distance-key matrix row i
// key[i][j] = (float_bits(D[i][j]) & 0xFFFFFF00) | j
// ---------------------------------------------------------------------------
__global__ __launch_bounds__(256) void k_dist() {
    const int i   = blockIdx.x;
    const int tid = threadIdx.x;

    __shared__ float sf[N_SEQ * NV];
    __shared__ unsigned smin[8], smax[8];

    for (int idx = tid; idx < N_SEQ * NV; idx += 256)
        sf[idx] = g_feat[idx];
    __syncthreads();

    unsigned lmin = INFK, lmax = 0u;
    for (int idx = tid; idx < N_SEQ * NV; idx += 256) {
        unsigned b = __float_as_uint(sf[idx]);
        lmin = min(lmin, b);
        lmax = max(lmax, b);
    }
    lmin = __reduce_min_sync(0xFFFFFFFFu, lmin);
    lmax = __reduce_max_sync(0xFFFFFFFFu, lmax);
    if ((tid & 31) == 0) { smin[tid >> 5] = lmin; smax[tid >> 5] = lmax; }
    __syncthreads();
    unsigned gmn = smin[0], gmx = smax[0];
    #pragma unroll
    for (int w = 1; w < 8; w++) { gmn = min(gmn, smin[w]); gmx = max(gmx, smax[w]); }
    const float inv = 1.0f / (__uint_as_float(gmx) - __uint_as_float(gmn));

    float fi[NV];
    #pragma unroll
    for (int d = 0; d < NV; d++) fi[d] = sf[i * NV + d];

    float ss = 0.f;
    #pragma unroll
    for (int d = 0; d < NV; d++) {
        float df = (fi[d] - sf[tid * NV + d]) * inv;
        ss += df * df;
    }
    g_Dk[i * N_SEQ + tid] = (__float_as_uint(sqrtf(ss)) & 0xFFFFFF00u) | (unsigned)tid;
}

// ---------------------------------------------------------------------------
// K3: single-warp Prim MST, 100% SMEM row fetches via symmetry:
//   node k -> lane (k&31), slot (k>>5)   [interleaved ownership]
//   j <  RZ : direct   sBuf[j*257 + k]                (banks j+l: conflict-free)
//   j >= RZ : k <  RZ : sBuf[k*257 + j]  + repack idx (banks l+j: conflict-free)
//             k >= RZ : sBuf[TBASE + (j-RZ)*43 + (k-RZ)]  (pre-packed)
// Branchless index SELs; no generic/global loads; no L2 on the chain.
// ---------------------------------------------------------------------------
__global__ __launch_bounds__(512) void k_mst(const float* __restrict__ centres,
                                             const float* __restrict__ sharp,
                                             float* __restrict__ out) {
    extern __shared__ __align__(16) unsigned sBuf[];
    __shared__ float deaths[N_SEQ - 1];
    __shared__ float s_part2[8][NK];

    const int tid = threadIdx.x;

    // Fill main rows (coalesced LDG.32, near-conflict-free STS.32)
    #pragma unroll 4
    for (int idx = tid; idx < RZ * N_SEQ; idx += 512)
        sBuf[(idx >> 8) * SROW + (idx & 255)] = g_Dk[idx];
    // Fill tail-tail block (already packed with col idx)
    for (int idx = tid; idx < TAIL * TAIL; idx += 512) {
        const int a = idx / TAIL, b = idx - a * TAIL;
        sBuf[TBASE + a * TROW + b] = g_Dk[(RZ + a) * N_SEQ + (RZ + b)];
    }
    __syncthreads();

    if (tid < 32) {
        const int lane = tid;

        // per-slot node constants
        #define NODE(T) (lane + 32 * (T))
        // init keys from row 0 of the matrix
        #define KINIT(T) unsigned k##T = sBuf[NODE(T)];
        KINIT(0) KINIT(1) KINIT(2) KINIT(3) KINIT(4) KINIT(5) KINIT(6) KINIT(7)
        #undef KINIT
        if (lane == 0) k0 = INFK;                 // node 0 starts in the tree

        unsigned m = min(min(min(k0, k1), min(k2, k3)),
                         min(min(k4, k5), min(k6, k7)));

        for (int it = 0; it < N_SEQ - 1; ++it) {
            unsigned g;
            asm volatile("redux.sync.min.u32 %0, %1, 0xffffffff;"
                         : "=r"(g) : "r"(m));
            const int j = (int)(g & 0xFFu);
            if (lane == 0) deaths[it] = __uint_as_float(g & 0xFFFFFF00u);

            const bool jin       = (j < RZ);
            const unsigned rowB  = (unsigned)j * SROW;           // direct row base
            const unsigned tailB = TBASE + (unsigned)(j - RZ) * TROW; // tail row base

            // per-slot candidate fetch (all LDS.32, conflict-free)
            #define FETCH(T, TAILPRED)                                          \
                unsigned v##T;                                                   \
                {                                                                \
                    const unsigned idxA = rowB + (unsigned)NODE(T);              \
                    const unsigned idxB = (TAILPRED)                             \
                        ? (tailB + (unsigned)(NODE(T) - RZ))                     \
                        : ((unsigned)NODE(T) * SROW + (unsigned)j);              \
                    const unsigned raw  = sBuf[jin ? idxA : idxB];               \
                    v##T = (jin || (TAILPRED))                                   \
                        ? raw                                                    \
                        : ((raw & 0xFFFFFF00u) | (unsigned)NODE(T));             \
                }
            FETCH(0, false) FETCH(1, false) FETCH(2, false)
            FETCH(3, false) FETCH(4, false) FETCH(5, false)
            FETCH(6, (NODE(6) >= RZ))   // slot 6 straddles RZ=214 (lane>=22)
            FETCH(7, true)              // nodes 224..255 always tail
            #undef FETCH

            // off-chain-ish: remove extracted node j, recompute fixed min
            const bool own = ((j & 31) == lane);
            const int  tj  = j >> 5;
            #define RM(T) k##T = (own && (tj == (T))) ? INFK : k##T;
            RM(0) RM(1) RM(2) RM(3) RM(4) RM(5) RM(6) RM(7)
            #undef RM
            const unsigned mfix = min(min(min(k0, k1), min(k2, k3)),
                                      min(min(k4, k5), min(k6, k7)));

            // mask in-tree nodes, merge candidates
            #define CM(T)                                                \
                const unsigned c##T = (k##T == INFK) ? INFK : v##T;      \
                k##T = min(k##T, c##T);
            CM(0) CM(1) CM(2) CM(3) CM(4) CM(5) CM(6) CM(7)
            #undef CM
            const unsigned mc = min(min(min(c0, c1), min(c2, c3)),
                                    min(min(c4, c5), min(c6, c7)));
            m = min(mfix, mc);
        }
        #undef NODE
    }
    __syncthreads();

    // ---- Structure element layer ----
    {
        const int k    = tid & (NK - 1);
        const int part = tid >> 6;            // 0..7
        const float c0 = centres[2 * k];
        const float c1 = centres[2 * k + 1];
        const float s0 = sharp[2 * k];
        const float s1 = sharp[2 * k + 1];
        const float a  = c0 * c0 * s0 * s0;
        const float b  = s1 * s1;

        float acc = 0.f;
        const int e0 = part * 32;
        const int e1 = min(N_SEQ - 1, e0 + 32);
        for (int e = e0; e < e1; e++) {
            float d = deaths[e] - c1;
            acc += __expf(-(a + d * d * b));
        }
        s_part2[part][k] = acc;
    }
    __syncthreads();
    if (tid < NK) {
        float s = 0.f;
        #pragma unroll
        for (int p = 0; p < 8; p++) s += s_part2[p][tid];
        out[tid] = s;
    }
}

// ---------------------------------------------------------------------------
extern "C" void kernel_launch(void* const* d_in, const int* in_sizes, int n_in,
                              void* d_out, int out_size) {
    const float* x       = (const float*)d_in[0];
    const float* centres = (const float*)d_in[1];
    const float* sharp   = (const float*)d_in[2];
    float*       out     = (float*)d_out;

    const size_t mst_smem = (size_t)MST_SMEM_WORDS * sizeof(unsigned);  // ~227.2 KB
    cudaFuncSetAttribute(k_mst, cudaFuncAttributeMaxDynamicSharedMemorySize, (int)mst_smem);

    k_meanfeat<<<N_SEQ, 400>>>(x);
    k_dist<<<N_SEQ, 256>>>();
    k_mst<<<1, 512, mst_smem>>>(centres, sharp, out);
}

// round 14
// speedup vs baseline: 1.2650x; 1.2588x over previous
#include <cuda_runtime.h>
#include <cuda_bf16.h>
#include <stdint.h>

// Shapes (fixed by the problem)
#define N_SEQ 256      // batch
#define NC    3        // coord channels
#define NT    256      // time
#define NV    25       // joints
#define NK    64       // structure elements
#define INF32 0xFFFFFFFFu
#define INF64 0xFFFFFFFFFFFFFFFFull

// Scratch (device globals — no allocation allowed)
__device__ __align__(16) float    g_feat[N_SEQ * NV];
__device__ __align__(16) unsigned g_Dk[N_SEQ * N_SEQ];   // packed (dist24|idx8) keys

// ---------------------------------------------------------------------------
// K1: per-sequence mean over (c,t), then feat[n,j] = || m[n,:] - m[n,j] ||
// block = 400 threads: joint of element t+400k == t%25 (400%25==0)
// ---------------------------------------------------------------------------
__global__ __launch_bounds__(400) void k_meanfeat(const float* __restrict__ x) {
    __shared__ float s_part[16][NV];
    __shared__ float s_m[NV];

    const int n   = blockIdx.x;
    const int tid = threadIdx.x;            // 0..399
    const float* p = x + (size_t)n * (NC * NT * NV) + tid;

    float a0 = 0.f, a1 = 0.f, a2 = 0.f, a3 = 0.f;
    float a4 = 0.f, a5 = 0.f, a6 = 0.f, a7 = 0.f;
    #pragma unroll
    for (int i = 0; i < 6; i++) {           // 48 = 19200/400 elements/thread
        const float* q = p + i * 8 * 400;
        a0 += q[0 * 400]; a1 += q[1 * 400]; a2 += q[2 * 400]; a3 += q[3 * 400];
        a4 += q[4 * 400]; a5 += q[5 * 400]; a6 += q[6 * 400]; a7 += q[7 * 400];
    }
    s_part[tid / 25][tid % 25] = ((a0 + a1) + (a2 + a3)) + ((a4 + a5) + (a6 + a7));
    __syncthreads();

    if (tid < NV) {
        float s = 0.f;
        #pragma unroll
        for (int g = 0; g < 16; g++) s += s_part[g][tid];
        s_m[tid] = s * (1.0f / (NC * NT));
    }
    __syncthreads();

    if (tid < NV) {
        const float mj = s_m[tid];
        float ss = 0.f;
        #pragma unroll
        for (int i = 0; i < NV; i++) {
            float d = s_m[i] - mj;
            ss += d * d;
        }
        g_feat[n * NV + tid] = sqrtf(ss);
    }
}

// ---------------------------------------------------------------------------
// K2: global min/max normalization + PACKED distance-key matrix row i
// key[i][j] = (float_bits(D[i][j]) & 0xFFFFFF00) | j     (D symmetric bitwise)
// ---------------------------------------------------------------------------
__global__ __launch_bounds__(256) void k_dist() {
    const int i   = blockIdx.x;
    const int tid = threadIdx.x;

    __shared__ float sf[N_SEQ * NV];
    __shared__ unsigned smin[8], smax[8];

    for (int idx = tid; idx < N_SEQ * NV; idx += 256)
        sf[idx] = g_feat[idx];
    __syncthreads();

    unsigned lmin = INF32, lmax = 0u;
    for (int idx = tid; idx < N_SEQ * NV; idx += 256) {
        unsigned b = __float_as_uint(sf[idx]);
        lmin = min(lmin, b);
        lmax = max(lmax, b);
    }
    lmin = __reduce_min_sync(0xFFFFFFFFu, lmin);
    lmax = __reduce_max_sync(0xFFFFFFFFu, lmax);
    if ((tid & 31) == 0) { smin[tid >> 5] = lmin; smax[tid >> 5] = lmax; }
    __syncthreads();
    unsigned gmn = smin[0], gmx = smax[0];
    #pragma unroll
    for (int w = 1; w < 8; w++) { gmn = min(gmn, smin[w]); gmx = max(gmx, smax[w]); }
    const float inv = 1.0f / (__uint_as_float(gmx) - __uint_as_float(gmn));

    float fi[NV];
    #pragma unroll
    for (int d = 0; d < NV; d++) fi[d] = sf[i * NV + d];

    float ss = 0.f;
    #pragma unroll
    for (int d = 0; d < NV; d++) {
        float df = (fi[d] - sf[tid * NV + d]) * inv;
        ss += df * df;
    }
    g_Dk[i * N_SEQ + tid] = (__float_as_uint(sqrtf(ss)) & 0xFFFFFF00u) | (unsigned)tid;
}

// ---------------------------------------------------------------------------
// K3: BORUVKA MST (parallel, <=8 rounds, no serial 255-iteration chain).
// Weights: canonical 48-bit (d24<<16)|(min<<8)|max -> globally distinct &
// symmetric => unique MST, ptr-graph cycles are exactly 2-cycles.
// Deaths land at deterministic (round, comp) slots, padded with 1e30 (exp->0).
// grid = 1, block = 512.
// ---------------------------------------------------------------------------
__global__ __launch_bounds__(512) void k_boruvka(const float* __restrict__ centres,
                                                 const float* __restrict__ sharp,
                                                 float* __restrict__ out) {
    __shared__ unsigned           slab[64];        // 256 node labels as bytes
    __shared__ unsigned long long compMin[256];    // per-component canonical min edge
    __shared__ unsigned           ptr_[256];       // union pointers
    __shared__ float              deaths2[8 * 256];
    __shared__ float              s_part2[8][NK];
    __shared__ int                accCnt;

    unsigned char* lbl8 = reinterpret_cast<unsigned char*>(slab);
    const int tid  = threadIdx.x;
    const int w    = tid >> 5;       // warp 0..15
    const int lane = tid & 31;
    const int hl   = lane >> 4;      // half-warp id
    const int li   = lane & 15;      // lane within half

    if (tid < 256) lbl8[tid] = (unsigned char)tid;
    for (int i = tid; i < 8 * 256; i += 512) deaths2[i] = 1e30f;
    if (tid == 0) accCnt = 0;
    __syncthreads();

    for (int rd = 0; rd < 8; ++rd) {
        const int acc = accCnt;                    // uniform: read after a bar
        if (acc < 255) {                           // uniform guard -> bars legal
            if (tid < 256) compMin[tid] = INF64;
            __syncthreads();

            // ---- scan: 8 passes; each warp handles 2 rows (one per half-warp)
            #pragma unroll 1
            for (int p = 0; p < 8; ++p) {
                const int r = (p << 5) + (w << 1) + hl;
                const unsigned myLbl = lbl8[r];
                const unsigned my4   = myLbl * 0x01010101u;
                const uint4* rowp = reinterpret_cast<const uint4*>(g_Dk + r * N_SEQ);
                unsigned m = INF32;
                #pragma unroll
                for (int i = 0; i < 4; ++i) {
                    const int q = li + (i << 4);           // uint4 index (coalesced)
                    const uint4 v = rowp[q];
                    const unsigned lw = slab[q];           // 4 labels of cols 4q..4q+3
                    const unsigned eq = __vcmpeq4(lw, my4);// 0xFF where same comp
                    const unsigned c0 = (eq & 0x000000FFu) ? INF32 : v.x;
                    const unsigned c1 = (eq & 0x0000FF00u) ? INF32 : v.y;
                    const unsigned c2 = (eq & 0x00FF0000u) ? INF32 : v.z;
                    const unsigned c3 = (eq & 0xFF000000u) ? INF32 : v.w;
                    m = min(m, min(min(c0, c1), min(c2, c3)));
                }
                // half-warp (16-lane) min reduction
                m = min(m, __shfl_xor_sync(0xFFFFFFFFu, m, 8, 16));
                m = min(m, __shfl_xor_sync(0xFFFFFFFFu, m, 4, 16));
                m = min(m, __shfl_xor_sync(0xFFFFFFFFu, m, 2, 16));
                m = min(m, __shfl_xor_sync(0xFFFFFFFFu, m, 1, 16));
                if (li == 0 && m != INF32) {
                    const unsigned k   = m & 0xFFu;
                    const unsigned d24 = m & 0xFFFFFF00u;
                    const unsigned mn  = min((unsigned)r, k);
                    const unsigned mx  = (unsigned)r + k - mn;
                    const unsigned long long cw =
                        ((unsigned long long)d24 << 16) | (mn << 8) | mx;
                    atomicMin(&compMin[myLbl], cw);
                }
            }
            __syncthreads();

            // ---- choose target component per component
            unsigned long long wv = INF64;
            if (tid < 256) {
                wv = compMin[tid];
                unsigned tgt = (unsigned)tid;
                if (wv != INF64) {
                    const unsigned mn  = (unsigned)(wv >> 8) & 0xFFu;
                    const unsigned mx  = (unsigned)wv & 0xFFu;
                    const unsigned lmn = lbl8[mn], lmx = lbl8[mx];
                    tgt = (lmn == (unsigned)tid) ? lmx : lmn;
                }
                ptr_[tid] = tgt;
            }
            __syncthreads();

            // ---- break 2-cycles: smaller index becomes root
            bool mut = false;
            if (tid < 256) {
                const unsigned t2 = ptr_[tid];
                mut = (t2 != (unsigned)tid) && (ptr_[t2] == (unsigned)tid)
                      && ((unsigned)tid < t2);
            }
            __syncthreads();
            if (tid < 256 && mut) ptr_[tid] = (unsigned)tid;
            __syncthreads();

            // ---- accept: every non-root contributes exactly one MST edge
            if (tid < 256) {
                if (ptr_[tid] != (unsigned)tid) {
                    deaths2[(rd << 8) + tid] = __uint_as_float((unsigned)(wv >> 16));
                    atomicAdd(&accCnt, 1);
                }
            }

            // ---- pointer doubling (depth <= 256 -> 8 steps)
            for (int s = 0; s < 8; ++s) {
                unsigned a = 0;
                __syncthreads();
                if (tid < 256) a = ptr_[ptr_[tid]];
                __syncthreads();
                if (tid < 256) ptr_[tid] = a;
            }
            __syncthreads();

            // ---- relabel nodes to their component roots
            unsigned nl = 0;
            if (tid < 256) nl = ptr_[lbl8[tid]];
            __syncthreads();
            if (tid < 256) lbl8[tid] = (unsigned char)nl;
            __syncthreads();
        }
    }

    // ---- Structure element layer over 8x256 slots (invalid = 1e30 -> skipped;
    //      whole warp shares a slot -> uniform branch)
    {
        const int k    = tid & (NK - 1);
        const int part = tid >> 6;            // 0..7
        const float c0 = centres[2 * k];
        const float c1 = centres[2 * k + 1];
        const float s0 = sharp[2 * k];
        const float s1 = sharp[2 * k + 1];
        const float a  = c0 * c0 * s0 * s0;
        const float b  = s1 * s1;

        float acc2 = 0.f;
        const int e0 = part * 256;
        for (int e = e0; e < e0 + 256; e++) {
            const float dv = deaths2[e];
            if (dv < 1e29f) {
                const float d = dv - c1;
                acc2 += __expf(-(a + d * d * b));
            }
        }
        s_part2[part][k] = acc2;
    }
    __syncthreads();
    if (tid < NK) {
        float s = 0.f;
        #pragma unroll
        for (int p = 0; p < 8; p++) s += s_part2[p][tid];
        out[tid] = s;
    }
}

// ---------------------------------------------------------------------------
extern "C" void kernel_launch(void* const* d_in, const int* in_sizes, int n_in,
                              void* d_out, int out_size) {
    const float* x       = (const float*)d_in[0];
    const float* centres = (const float*)d_in[1];
    const float* sharp   = (const float*)d_in[2];
    float*       out     = (float*)d_out;

    k_meanfeat<<<N_SEQ, 400>>>(x);
    k_dist<<<N_SEQ, 256>>>();
    k_boruvka<<<1, 512>>>(centres, sharp, out);
}

// round 15
// speedup vs baseline: 1.3142x; 1.0389x over previous
#include <cuda_runtime.h>
#include <cuda_bf16.h>
#include <stdint.h>

// Shapes (fixed by the problem)
#define N_SEQ 256      // batch
#define NC    3        // coord channels
#define NT    256      // time
#define NV    25       // joints
#define NK    64       // structure elements
#define INF32 0xFFFFFFFFu
#define INF64 0xFFFFFFFFFFFFFFFFull

// Scratch (device globals — no allocation allowed)
__device__ __align__(16) float    g_feat[N_SEQ * NV];
__device__ __align__(16) unsigned g_Dk[N_SEQ * N_SEQ];   // packed (dist24|idx8) keys

// ---------------------------------------------------------------------------
// K1: per-sequence mean over (c,t), then feat[n,j] = || m[n,:] - m[n,j] ||
// block = 400 threads: joint of element t+400k == t%25 (400%25==0)
// ---------------------------------------------------------------------------
__global__ __launch_bounds__(400) void k_meanfeat(const float* __restrict__ x) {
    __shared__ float s_part[16][NV];
    __shared__ float s_m[NV];

    const int n   = blockIdx.x;
    const int tid = threadIdx.x;            // 0..399
    const float* p = x + (size_t)n * (NC * NT * NV) + tid;

    float a0 = 0.f, a1 = 0.f, a2 = 0.f, a3 = 0.f;
    float a4 = 0.f, a5 = 0.f, a6 = 0.f, a7 = 0.f;
    #pragma unroll
    for (int i = 0; i < 6; i++) {           // 48 = 19200/400 elements/thread
        const float* q = p + i * 8 * 400;
        a0 += q[0 * 400]; a1 += q[1 * 400]; a2 += q[2 * 400]; a3 += q[3 * 400];
        a4 += q[4 * 400]; a5 += q[5 * 400]; a6 += q[6 * 400]; a7 += q[7 * 400];
    }
    s_part[tid / 25][tid % 25] = ((a0 + a1) + (a2 + a3)) + ((a4 + a5) + (a6 + a7));
    __syncthreads();

    if (tid < NV) {
        float s = 0.f;
        #pragma unroll
        for (int g = 0; g < 16; g++) s += s_part[g][tid];
        s_m[tid] = s * (1.0f / (NC * NT));
    }
    __syncthreads();

    if (tid < NV) {
        const float mj = s_m[tid];
        float ss = 0.f;
        #pragma unroll
        for (int i = 0; i < NV; i++) {
            float d = s_m[i] - mj;
            ss += d * d;
        }
        g_feat[n * NV + tid] = sqrtf(ss);
    }
}

// ---------------------------------------------------------------------------
// K2: global min/max normalization + PACKED distance-key matrix row i
// key[i][j] = (float_bits(D[i][j]) & 0xFFFFFF00) | j     (D symmetric bitwise)
// ---------------------------------------------------------------------------
__global__ __launch_bounds__(256) void k_dist() {
    const int i   = blockIdx.x;
    const int tid = threadIdx.x;

    __shared__ float sf[N_SEQ * NV];
    __shared__ unsigned smin[8], smax[8];

    for (int idx = tid; idx < N_SEQ * NV; idx += 256)
        sf[idx] = g_feat[idx];
    __syncthreads();

    unsigned lmin = INF32, lmax = 0u;
    for (int idx = tid; idx < N_SEQ * NV; idx += 256) {
        unsigned b = __float_as_uint(sf[idx]);
        lmin = min(lmin, b);
        lmax = max(lmax, b);
    }
    lmin = __reduce_min_sync(0xFFFFFFFFu, lmin);
    lmax = __reduce_max_sync(0xFFFFFFFFu, lmax);
    if ((tid & 31) == 0) { smin[tid >> 5] = lmin; smax[tid >> 5] = lmax; }
    __syncthreads();
    unsigned gmn = smin[0], gmx = smax[0];
    #pragma unroll
    for (int w = 1; w < 8; w++) { gmn = min(gmn, smin[w]); gmx = max(gmx, smax[w]); }
    const float inv = 1.0f / (__uint_as_float(gmx) - __uint_as_float(gmn));

    float fi[NV];
    #pragma unroll
    for (int d = 0; d < NV; d++) fi[d] = sf[i * NV + d];

    float ss = 0.f;
    #pragma unroll
    for (int d = 0; d < NV; d++) {
        float df = (fi[d] - sf[tid * NV + d]) * inv;
        ss += df * df;
    }
    g_Dk[i * N_SEQ + tid] = (__float_as_uint(sqrtf(ss)) & 0xFFFFFF00u) | (unsigned)tid;
}

// ---------------------------------------------------------------------------
// K3: BORUVKA MST (parallel, <=8 rounds, no serial 255-iteration chain).
// Weights: canonical 48-bit (d24<<16)|(min<<8)|max -> globally distinct &
// symmetric => unique MST, ptr-graph cycles are exactly 2-cycles.
// Deaths land at deterministic (round, comp) slots, padded with 1e30 (exp->0).
// grid = 1, block = 512.
// ---------------------------------------------------------------------------
__global__ __launch_bounds__(512) void k_boruvka(const float* __restrict__ centres,
                                                 const float* __restrict__ sharp,
                                                 float* __restrict__ out) {
    __shared__ unsigned           slab[64];        // 256 node labels as bytes
    __shared__ unsigned long long compMin[256];    // per-component canonical min edge
    __shared__ unsigned           ptr_[256];       // union pointers
    __shared__ float              deaths2[8 * 256];
    __shared__ float              s_part2[8][NK];
    __shared__ int                accCnt;

    unsigned char* lbl8 = reinterpret_cast<unsigned char*>(slab);
    const int tid  = threadIdx.x;
    const int w    = tid >> 5;       // warp 0..15
    const int lane = tid & 31;
    const int hl   = lane >> 4;      // half-warp id
    const int li   = lane & 15;      // lane within half

    if (tid < 256) lbl8[tid] = (unsigned char)tid;
    for (int i = tid; i < 8 * 256; i += 512) deaths2[i] = 1e30f;
    if (tid == 0) accCnt = 0;
    __syncthreads();

    for (int rd = 0; rd < 8; ++rd) {
        const int acc = accCnt;                    // uniform: read after a bar
        if (acc < 255) {                           // uniform guard -> bars legal
            if (tid < 256) compMin[tid] = INF64;
            __syncthreads();

            // ---- scan: 8 passes; each warp handles 2 rows (one per half-warp)
            #pragma unroll 1
            for (int p = 0; p < 8; ++p) {
                const int r = (p << 5) + (w << 1) + hl;
                const unsigned myLbl = lbl8[r];
                const unsigned my4   = myLbl * 0x01010101u;
                const uint4* rowp = reinterpret_cast<const uint4*>(g_Dk + r * N_SEQ);
                unsigned m = INF32;
                #pragma unroll
                for (int i = 0; i < 4; ++i) {
                    const int q = li + (i << 4);           // uint4 index (coalesced)
                    const uint4 v = rowp[q];
                    const unsigned lw = slab[q];           // 4 labels of cols 4q..4q+3
                    const unsigned eq = __vcmpeq4(lw, my4);// 0xFF where same comp
                    const unsigned c0 = (eq & 0x000000FFu) ? INF32 : v.x;
                    const unsigned c1 = (eq & 0x0000FF00u) ? INF32 : v.y;
                    const unsigned c2 = (eq & 0x00FF0000u) ? INF32 : v.z;
                    const unsigned c3 = (eq & 0xFF000000u) ? INF32 : v.w;
                    m = min(m, min(min(c0, c1), min(c2, c3)));
                }
                // half-warp (16-lane) min reduction
                m = min(m, __shfl_xor_sync(0xFFFFFFFFu, m, 8, 16));
                m = min(m, __shfl_xor_sync(0xFFFFFFFFu, m, 4, 16));
                m = min(m, __shfl_xor_sync(0xFFFFFFFFu, m, 2, 16));
                m = min(m, __shfl_xor_sync(0xFFFFFFFFu, m, 1, 16));
                if (li == 0 && m != INF32) {
                    const unsigned k   = m & 0xFFu;
                    const unsigned d24 = m & 0xFFFFFF00u;
                    const unsigned mn  = min((unsigned)r, k);
                    const unsigned mx  = (unsigned)r + k - mn;
                    const unsigned long long cw =
                        ((unsigned long long)d24 << 16) | (mn << 8) | mx;
                    atomicMin(&compMin[myLbl], cw);
                }
            }
            __syncthreads();

            // ---- choose target component per component
            unsigned long long wv = INF64;
            if (tid < 256) {
                wv = compMin[tid];
                unsigned tgt = (unsigned)tid;
                if (wv != INF64) {
                    const unsigned mn  = (unsigned)(wv >> 8) & 0xFFu;
                    const unsigned mx  = (unsigned)wv & 0xFFu;
                    const unsigned lmn = lbl8[mn], lmx = lbl8[mx];
                    tgt = (lmn == (unsigned)tid) ? lmx : lmn;
                }
                ptr_[tid] = tgt;
            }
            __syncthreads();

            // ---- break 2-cycles: smaller index becomes root
            bool mut = false;
            if (tid < 256) {
                const unsigned t2 = ptr_[tid];
                mut = (t2 != (unsigned)tid) && (ptr_[t2] == (unsigned)tid)
                      && ((unsigned)tid < t2);
            }
            __syncthreads();
            if (tid < 256 && mut) ptr_[tid] = (unsigned)tid;
            __syncthreads();

            // ---- accept: every non-root contributes exactly one MST edge
            if (tid < 256) {
                if (ptr_[tid] != (unsigned)tid) {
                    deaths2[(rd << 8) + tid] = __uint_as_float((unsigned)(wv >> 16));
                    atomicAdd(&accCnt, 1);
                }
            }

            // ---- pointer doubling (depth <= 256 -> 8 steps)
            for (int s = 0; s < 8; ++s) {
                unsigned a = 0;
                __syncthreads();
                if (tid < 256) a = ptr_[ptr_[tid]];
                __syncthreads();
                if (tid < 256) ptr_[tid] = a;
            }
            __syncthreads();

            // ---- relabel nodes to their component roots
            unsigned nl = 0;
            if (tid < 256) nl = ptr_[lbl8[tid]];
            __syncthreads();
            if (tid < 256) lbl8[tid] = (unsigned char)nl;
            __syncthreads();
        }
    }

    // ---- Structure element layer over 8x256 slots (invalid = 1e30 -> skipped;
    //      whole warp shares a slot -> uniform branch)
    {
        const int k    = tid & (NK - 1);
        const int part = tid >> 6;            // 0..7
        const float c0 = centres[2 * k];
        const float c1 = centres[2 * k + 1];
        const float s0 = sharp[2 * k];
        const float s1 = sharp[2 * k + 1];
        const float a  = c0 * c0 * s0 * s0;
        const float b  = s1 * s1;

        float acc2 = 0.f;
        const int e0 = part * 256;
        for (int e = e0; e < e0 + 256; e++) {
            const float dv = deaths2[e];
            if (dv < 1e29f) {
                const float d = dv - c1;
                acc2 += __expf(-(a + d * d * b));
            }
        }
        s_part2[part][k] = acc2;
    }
    __syncthreads();
    if (tid < NK) {
        float s = 0.f;
        #pragma unroll
        for (int p = 0; p < 8; p++) s += s_part2[p][tid];
        out[tid] = s;
    }
}

// ---------------------------------------------------------------------------
extern "C" void kernel_launch(void* const* d_in, const int* in_sizes, int n_in,
                              void* d_out, int out_size) {
    const float* x       = (const float*)d_in[0];
    const float* centres = (const float*)d_in[1];
    const float* sharp   = (const float*)d_in[2];
    float*       out     = (float*)d_out;

    k_meanfeat<<<N_SEQ, 400>>>(x);
    k_dist<<<N_SEQ, 256>>>();
    k_boruvka<<<1, 512>>>(centres, sharp, out);
}

// round 16
// speedup vs baseline: 1.3174x; 1.0024x over previous
#include <cuda_runtime.h>
#include <cuda_bf16.h>
#include <stdint.h>

// Shapes (fixed by the problem)
#define N_SEQ 256      // batch
#define NC    3        // coord channels
#define NT    256      // time
#define NV    25       // joints
#define NK    64       // structure elements
#define INF32 0xFFFFFFFFu
#define INF64 0xFFFFFFFFFFFFFFFFull

// Scratch (device globals — no allocation allowed)
__device__ __align__(16) float    g_feat[N_SEQ * NV];
__device__ __align__(16) unsigned g_Dk[N_SEQ * N_SEQ];   // packed (dist24|idx8) keys

// ---------------------------------------------------------------------------
// K1: per-sequence mean over (c,t), then feat[n,j] = || m[n,:] - m[n,j] ||
// block = 400 threads: joint of element t+400k == t%25 (400%25==0)
// ---------------------------------------------------------------------------
__global__ __launch_bounds__(400) void k_meanfeat(const float* __restrict__ x) {
    __shared__ float s_part[16][NV];
    __shared__ float s_m[NV];

    const int n   = blockIdx.x;
    const int tid = threadIdx.x;            // 0..399
    const float* p = x + (size_t)n * (NC * NT * NV) + tid;

    float a0 = 0.f, a1 = 0.f, a2 = 0.f, a3 = 0.f;
    float a4 = 0.f, a5 = 0.f, a6 = 0.f, a7 = 0.f;
    #pragma unroll
    for (int i = 0; i < 6; i++) {           // 48 = 19200/400 elements/thread
        const float* q = p + i * 8 * 400;
        a0 += q[0 * 400]; a1 += q[1 * 400]; a2 += q[2 * 400]; a3 += q[3 * 400];
        a4 += q[4 * 400]; a5 += q[5 * 400]; a6 += q[6 * 400]; a7 += q[7 * 400];
    }
    s_part[tid / 25][tid % 25] = ((a0 + a1) + (a2 + a3)) + ((a4 + a5) + (a6 + a7));
    __syncthreads();

    if (tid < NV) {
        float s = 0.f;
        #pragma unroll
        for (int g = 0; g < 16; g++) s += s_part[g][tid];
        s_m[tid] = s * (1.0f / (NC * NT));
    }
    __syncthreads();

    if (tid < NV) {
        const float mj = s_m[tid];
        float ss = 0.f;
        #pragma unroll
        for (int i = 0; i < NV; i++) {
            float d = s_m[i] - mj;
            ss += d * d;
        }
        g_feat[n * NV + tid] = sqrtf(ss);
    }
}

// ---------------------------------------------------------------------------
// K2: global min/max normalization + PACKED distance-key matrix row i
// key[i][j] = (float_bits(D[i][j]) & 0xFFFFFF00) | j     (D symmetric bitwise)
// ---------------------------------------------------------------------------
__global__ __launch_bounds__(256) void k_dist() {
    const int i   = blockIdx.x;
    const int tid = threadIdx.x;

    __shared__ float sf[N_SEQ * NV];
    __shared__ unsigned smin[8], smax[8];

    for (int idx = tid; idx < N_SEQ * NV; idx += 256)
        sf[idx] = g_feat[idx];
    __syncthreads();

    unsigned lmin = INF32, lmax = 0u;
    for (int idx = tid; idx < N_SEQ * NV; idx += 256) {
        unsigned b = __float_as_uint(sf[idx]);
        lmin = min(lmin, b);
        lmax = max(lmax, b);
    }
    lmin = __reduce_min_sync(0xFFFFFFFFu, lmin);
    lmax = __reduce_max_sync(0xFFFFFFFFu, lmax);
    if ((tid & 31) == 0) { smin[tid >> 5] = lmin; smax[tid >> 5] = lmax; }
    __syncthreads();
    unsigned gmn = smin[0], gmx = smax[0];
    #pragma unroll
    for (int w = 1; w < 8; w++) { gmn = min(gmn, smin[w]); gmx = max(gmx, smax[w]); }
    const float inv = 1.0f / (__uint_as_float(gmx) - __uint_as_float(gmn));

    float fi[NV];
    #pragma unroll
    for (int d = 0; d < NV; d++) fi[d] = sf[i * NV + d];

    float ss = 0.f;
    #pragma unroll
    for (int d = 0; d < NV; d++) {
        float df = (fi[d] - sf[tid * NV + d]) * inv;
        ss += df * df;
    }
    g_Dk[i * N_SEQ + tid] = (__float_as_uint(sqrtf(ss)) & 0xFFFFFF00u) | (unsigned)tid;
}

// ---------------------------------------------------------------------------
// K3: BORUVKA MST (parallel, <=8 rounds, no serial 255-iteration chain).
// Weights: canonical 48-bit (d24<<16)|(min<<8)|max -> globally distinct &
// symmetric => unique MST, ptr-graph cycles are exactly 2-cycles.
// Deaths land at deterministic (round, comp) slots, padded with 1e30 (exp->0).
// grid = 1, block = 512.
// ---------------------------------------------------------------------------
__global__ __launch_bounds__(512) void k_boruvka(const float* __restrict__ centres,
                                                 const float* __restrict__ sharp,
                                                 float* __restrict__ out) {
    __shared__ unsigned           slab[64];        // 256 node labels as bytes
    __shared__ unsigned long long compMin[256];    // per-component canonical min edge
    __shared__ unsigned           ptr_[256];       // union pointers
    __shared__ float              deaths2[8 * 256];
    __shared__ float              s_part2[8][NK];
    __shared__ int                accCnt;

    unsigned char* lbl8 = reinterpret_cast<unsigned char*>(slab);
    const int tid  = threadIdx.x;
    const int w    = tid >> 5;       // warp 0..15
    const int lane = tid & 31;
    const int hl   = lane >> 4;      // half-warp id
    const int li   = lane & 15;      // lane within half

    if (tid < 256) lbl8[tid] = (unsigned char)tid;
    for (int i = tid; i < 8 * 256; i += 512) deaths2[i] = 1e30f;
    if (tid == 0) accCnt = 0;
    __syncthreads();

    for (int rd = 0; rd < 8; ++rd) {
        const int acc = accCnt;                    // uniform: read after a bar
        if (acc < 255) {                           // uniform guard -> bars legal
            if (tid < 256) compMin[tid] = INF64;
            __syncthreads();

            // ---- scan: 8 passes; each warp handles 2 rows (one per half-warp)
            #pragma unroll 1
            for (int p = 0; p < 8; ++p) {
                const int r = (p << 5) + (w << 1) + hl;
                const unsigned myLbl = lbl8[r];
                const unsigned my4   = myLbl * 0x01010101u;
                const uint4* rowp = reinterpret_cast<const uint4*>(g_Dk + r * N_SEQ);
                unsigned m = INF32;
                #pragma unroll
                for (int i = 0; i < 4; ++i) {
                    const int q = li + (i << 4);           // uint4 index (coalesced)
                    const uint4 v = rowp[q];
                    const unsigned lw = slab[q];           // 4 labels of cols 4q..4q+3
                    const unsigned eq = __vcmpeq4(lw, my4);// 0xFF where same comp
                    const unsigned c0 = (eq & 0x000000FFu) ? INF32 : v.x;
                    const unsigned c1 = (eq & 0x0000FF00u) ? INF32 : v.y;
                    const unsigned c2 = (eq & 0x00FF0000u) ? INF32 : v.z;
                    const unsigned c3 = (eq & 0xFF000000u) ? INF32 : v.w;
                    m = min(m, min(min(c0, c1), min(c2, c3)));
                }
                // half-warp (16-lane) min reduction
                m = min(m, __shfl_xor_sync(0xFFFFFFFFu, m, 8, 16));
                m = min(m, __shfl_xor_sync(0xFFFFFFFFu, m, 4, 16));
                m = min(m, __shfl_xor_sync(0xFFFFFFFFu, m, 2, 16));
                m = min(m, __shfl_xor_sync(0xFFFFFFFFu, m, 1, 16));
                if (li == 0 && m != INF32) {
                    const unsigned k   = m & 0xFFu;
                    const unsigned d24 = m & 0xFFFFFF00u;
                    const unsigned mn  = min((unsigned)r, k);
                    const unsigned mx  = (unsigned)r + k - mn;
                    const unsigned long long cw =
                        ((unsigned long long)d24 << 16) | (mn << 8) | mx;
                    atomicMin(&compMin[myLbl], cw);
                }
            }
            __syncthreads();

            // ---- choose target component per component
            unsigned long long wv = INF64;
            if (tid < 256) {
                wv = compMin[tid];
                unsigned tgt = (unsigned)tid;
                if (wv != INF64) {
                    const unsigned mn  = (unsigned)(wv >> 8) & 0xFFu;
                    const unsigned mx  = (unsigned)wv & 0xFFu;
                    const unsigned lmn = lbl8[mn], lmx = lbl8[mx];
                    tgt = (lmn == (unsigned)tid) ? lmx : lmn;
                }
                ptr_[tid] = tgt;
            }
            __syncthreads();

            // ---- break 2-cycles: smaller index becomes root
            bool mut = false;
            if (tid < 256) {
                const unsigned t2 = ptr_[tid];
                mut = (t2 != (unsigned)tid) && (ptr_[t2] == (unsigned)tid)
                      && ((unsigned)tid < t2);
            }
            __syncthreads();
            if (tid < 256 && mut) ptr_[tid] = (unsigned)tid;
            __syncthreads();

            // ---- accept: every non-root contributes exactly one MST edge
            if (tid < 256) {
                if (ptr_[tid] != (unsigned)tid) {
                    deaths2[(rd << 8) + tid] = __uint_as_float((unsigned)(wv >> 16));
                    atomicAdd(&accCnt, 1);
                }
            }

            // ---- pointer doubling (depth <= 256 -> 8 steps)
            for (int s = 0; s < 8; ++s) {
                unsigned a = 0;
                __syncthreads();
                if (tid < 256) a = ptr_[ptr_[tid]];
                __syncthreads();
                if (tid < 256) ptr_[tid] = a;
            }
            __syncthreads();

            // ---- relabel nodes to their component roots
            unsigned nl = 0;
            if (tid < 256) nl = ptr_[lbl8[tid]];
            __syncthreads();
            if (tid < 256) lbl8[tid] = (unsigned char)nl;
            __syncthreads();
        }
    }

    // ---- Structure element layer over 8x256 slots (invalid = 1e30 -> skipped;
    //      whole warp shares a slot -> uniform branch)
    {
        const int k    = tid & (NK - 1);
        const int part = tid >> 6;            // 0..7
        const float c0 = centres[2 * k];
        const float c1 = centres[2 * k + 1];
        const float s0 = sharp[2 * k];
        const float s1 = sharp[2 * k + 1];
        const float a  = c0 * c0 * s0 * s0;
        const float b  = s1 * s1;

        float acc2 = 0.f;
        const int e0 = part * 256;
        for (int e = e0; e < e0 + 256; e++) {
            const float dv = deaths2[e];
            if (dv < 1e29f) {
                const float d = dv - c1;
                acc2 += __expf(-(a + d * d * b));
            }
        }
        s_part2[part][k] = acc2;
    }
    __syncthreads();
    if (tid < NK) {
        float s = 0.f;
        #pragma unroll
        for (int p = 0; p < 8; p++) s += s_part2[p][tid];
        out[tid] = s;
    }
}

// ---------------------------------------------------------------------------
extern "C" void kernel_launch(void* const* d_in, const int* in_sizes, int n_in,
                              void* d_out, int out_size) {
    const float* x       = (const float*)d_in[0];
    const float* centres = (const float*)d_in[1];
    const float* sharp   = (const float*)d_in[2];
    float*       out     = (float*)d_out;

    k_meanfeat<<<N_SEQ, 400>>>(x);
    k_dist<<<N_SEQ, 256>>>();
    k_boruvka<<<1, 512>>>(centres, sharp, out);
}